// round 7
// baseline (speedup 1.0000x reference)
#include <cuda_runtime.h>
#include <math.h>

#define NB   32
#define NP   8732
#define NC   21
#define TOPK 200
#define NT   256
#define NP4  (NP / 4)      // 2183
#define NBIN 8192
#define FULLM 0xFFFFFFFFu

// Transposed, thresholded, order-mapped confidences: key32[b][c][p]
__device__ unsigned g_confT[(size_t)NB * NC * NP];
// Per-(b,c) pivot: (t0 << 51) | overflow_flag(bit0)
__device__ unsigned long long g_pivot[NB * NC];

// ---------------------------------------------------------------------------
// Kernel 1: transpose + threshold + monotonic map (vectorized, no atomics)
// ---------------------------------------------------------------------------
#define TP  512
#define S2S 516
__global__ void transpose_kernel(const float* __restrict__ conf) {
    __shared__ float s2[NC * S2S];
    const int nt  = (NP + TP - 1) / TP;     // 18
    const int b   = blockIdx.x / nt;
    const int t   = blockIdx.x % nt;
    const int p0  = t * TP;
    const int np  = min(TP, NP - p0);
    const float* src = conf + ((size_t)b * NP + p0) * NC;
    const int n  = np * NC;
    const int nv = n >> 2;
    const float4* src4 = (const float4*)src;

    for (int i = threadIdx.x; i < nv; i += blockDim.x) {
        float4 v = src4[i];
        int li = i * 4;
        #pragma unroll
        for (int q = 0; q < 4; q++) {
            int e = li + q;
            int p = e / NC;
            int c = e - p * NC;
            float f = (q == 0) ? v.x : (q == 1) ? v.y : (q == 2) ? v.z : v.w;
            s2[c * S2S + p] = f;
        }
    }
    __syncthreads();

    const int ng = np >> 2;
    for (int idx = threadIdx.x; idx < NC * ng; idx += blockDim.x) {
        int c = idx / ng;
        int g = idx - c * ng;
        int p = g * 4;
        float4 v = *(const float4*)&s2[c * S2S + p];
        uint4 o;
        {
            float sv = (v.x > 0.01f) ? v.x : -1.0f;
            unsigned u = __float_as_uint(sv);
            o.x = (u & 0x80000000u) ? ~u : (u | 0x80000000u);
        }
        {
            float sv = (v.y > 0.01f) ? v.y : -1.0f;
            unsigned u = __float_as_uint(sv);
            o.y = (u & 0x80000000u) ? ~u : (u | 0x80000000u);
        }
        {
            float sv = (v.z > 0.01f) ? v.z : -1.0f;
            unsigned u = __float_as_uint(sv);
            o.z = (u & 0x80000000u) ? ~u : (u | 0x80000000u);
        }
        {
            float sv = (v.w > 0.01f) ? v.w : -1.0f;
            unsigned u = __float_as_uint(sv);
            o.w = (u & 0x80000000u) ? ~u : (u | 0x80000000u);
        }
        *(uint4*)(g_confT + ((size_t)b * NC + c) * NP + p0 + p) = o;
    }
}

// ---------------------------------------------------------------------------
// warp-aggregated smem histogram add (all 32 lanes converged)
__device__ __forceinline__ void aggHist(unsigned* hist, int d, bool in) {
    unsigned mm = __match_any_sync(FULLM, d);
    int lane = threadIdx.x & 31;
    if (in && lane == (__ffs(mm) - 1))
        atomicAdd(&hist[d], (unsigned)__popc(mm));
}

// ---------------------------------------------------------------------------
// Kernel 2: per-(b,c) smem histogram + pivot (reads keys from L2)
// ---------------------------------------------------------------------------
__global__ __launch_bounds__(NT, 7)
void pivot_kernel() {
    const int blk = blockIdx.x;
    if (blk % NC == 0) return;
    const int tid = threadIdx.x;
    const int lane = tid & 31;
    const int wid  = tid >> 5;

    __shared__ unsigned hist[NBIN];          // 32 KB
    __shared__ unsigned warpSums[8];
    __shared__ unsigned res[4];

    {
        uint4* h4 = (uint4*)hist;
        #pragma unroll
        for (int i = 0; i < NBIN / 4 / NT; i++)
            h4[i * NT + tid] = make_uint4(0, 0, 0, 0);
    }
    __syncthreads();

    const uint4* col4 = (const uint4*)(g_confT + (size_t)blk * NP);
    const int FULL_IT = NP4 / NT;            // 8
    const int TAIL    = NP4 - FULL_IT * NT;  // 135

    for (int it = 0; it <= FULL_IT; it++) {
        int i = it * NT + tid;
        bool valid = (it < FULL_IT) || (tid < TAIL);
        uint4 m4 = valid ? col4[i] : make_uint4(0, 0, 0, 0);
        aggHist(hist, valid ? (int)(m4.x >> 19) : 0x3FFF, valid);
        aggHist(hist, valid ? (int)(m4.y >> 19) : 0x3FFF, valid);
        aggHist(hist, valid ? (int)(m4.z >> 19) : 0x3FFF, valid);
        aggHist(hist, valid ? (int)(m4.w >> 19) : 0x3FFF, valid);
    }
    __syncthreads();

    // ---- parallel threshold over 8192 bins, descending; 32 bins/thread ----
    {
        int hi = 8191 - (tid << 5);          // covers bins hi-31 .. hi
        unsigned bins[32];
        {
            const uint4* b4 = (const uint4*)(hist + (hi - 31));
            #pragma unroll
            for (int q = 0; q < 8; q++) {
                uint4 v = b4[q];
                bins[q * 4 + 0] = v.x; bins[q * 4 + 1] = v.y;
                bins[q * 4 + 2] = v.z; bins[q * 4 + 3] = v.w;
            }
        }
        unsigned lsum = 0;
        #pragma unroll
        for (int q = 0; q < 32; q++) lsum += bins[q];

        unsigned inc = lsum;
        #pragma unroll
        for (int off = 1; off < 32; off <<= 1) {
            unsigned nn = __shfl_up_sync(FULLM, inc, off);
            if (lane >= off) inc += nn;
        }
        if (lane == 31) warpSums[wid] = inc;
        __syncthreads();
        if (wid == 0) {
            unsigned v = (lane < 8) ? warpSums[lane] : 0;
            #pragma unroll
            for (int off = 1; off < 8; off <<= 1) {
                unsigned nn = __shfl_up_sync(FULLM, v, off);
                if (lane >= off) v += nn;
            }
            if (lane < 8) warpSums[lane] = v;
        }
        __syncthreads();
        unsigned ex = (wid ? warpSums[wid - 1] : 0) + inc - lsum;
        if (ex <= TOPK && ex + lsum > TOPK) {   // unique crossing thread
            unsigned acc = ex;
            #pragma unroll
            for (int q = 0; q < 32; q++) {
                unsigned hv = bins[31 - q];      // bin (hi - q)
                if (acc + hv > TOPK) {
                    res[0] = (unsigned)(hi - q);
                    res[1] = acc;
                    res[2] = hv;
                    break;
                }
                acc += hv;
            }
        }
    }
    __syncthreads();
    if (tid == 0) {
        unsigned long long C = (unsigned long long)res[0] << 51;
        if (res[1] + res[2] > 512u) C |= 1ull;
        g_pivot[blk] = C;
    }
}

// ---------------------------------------------------------------------------
__device__ __forceinline__ float unmapf(unsigned m) {
    unsigned u = (m & 0x80000000u) ? (m ^ 0x80000000u) : ~m;
    return __uint_as_float(u);
}

// ---------------------------------------------------------------------------
// Kernel 3: collect >= C, sort, decode, NMS, write   (256 thr, 8 CTAs/SM)
// ---------------------------------------------------------------------------
__global__ __launch_bounds__(NT, 8)
void select_kernel(const float* __restrict__ loc,
                   const float* __restrict__ prior,
                   float* __restrict__ out) {
    const int blk = blockIdx.x;
    const int b   = blk / NC;
    const int c   = blk % NC;
    const int tid = threadIdx.x;
    const int lane = tid & 31;
    const int wid  = tid >> 5;
    float* outBase = out + (size_t)blk * (TOPK * 5);

    {
        float4* ob4 = (float4*)outBase;
        for (int i = tid; i < (TOPK * 5) / 4; i += NT)
            ob4[i] = make_float4(0.f, 0.f, 0.f, 0.f);
    }
    if (c == 0) return;

    __shared__ unsigned ctr[8];
    __shared__ unsigned long long defs[512];
    __shared__ float4   boxs[TOPK];
    __shared__ float    areas[TOPK];
    __shared__ float    scores[TOPK];
    __shared__ unsigned rows[TOPK * 8];
    __shared__ unsigned keepw[8];
    __shared__ unsigned validw[8];
    __shared__ unsigned hasroww[8];

    const uint4* col4 = (const uint4*)(g_confT + (size_t)blk * NP);
    const int FULL_IT = NP4 / NT;           // 8
    const int TAIL    = NP4 - FULL_IT * NT; // 135

    unsigned long long pv = g_pivot[blk];
    unsigned long long C  = pv & ~1ull;

    if (pv & 1ull) {
        // rare exact fallback: bitwise search for the 200th key
        unsigned long long Cp = (pv >> 51) << 51;
        for (int bit = 50; bit >= 0; bit--) {
            unsigned long long trial = Cp | (1ull << bit);
            if (tid == 0) ctr[7] = 0;
            __syncthreads();
            unsigned wcnt = 0;
            for (int it = 0; it <= FULL_IT; it++) {
                int i = it * NT + tid;
                bool valid = (it < FULL_IT) || (tid < TAIL);
                uint4 m4 = valid ? col4[i] : make_uint4(0, 0, 0, 0);
                #pragma unroll
                for (int q = 0; q < 4; q++) {
                    unsigned m = (q == 0) ? m4.x : (q == 1) ? m4.y : (q == 2) ? m4.z : m4.w;
                    unsigned idx = (unsigned)(i * 4 + q);
                    unsigned long long key =
                        ((unsigned long long)m << 32) | (unsigned)(~idx);
                    wcnt += __popc(__ballot_sync(FULLM, valid && key >= trial));
                }
            }
            if (lane == 0) atomicAdd(&ctr[7], wcnt);
            __syncthreads();
            if (ctr[7] >= TOPK) Cp = trial;
            __syncthreads();
        }
        C = Cp;
    }

    // ---------------- collect all keys >= C (32-bit compare fast path) -----
    const unsigned Cm = (unsigned)(C >> 32);
    const unsigned Cl = (unsigned)C;        // 0 in fast path
    if (tid == 0) ctr[0] = 0;
    __syncthreads();
    for (int it = 0; it <= FULL_IT; it++) {
        int i = it * NT + tid;
        bool valid = (it < FULL_IT) || (tid < TAIL);
        uint4 m4 = valid ? col4[i] : make_uint4(0, 0, 0, 0);
        #pragma unroll
        for (int q = 0; q < 4; q++) {
            unsigned m = (q == 0) ? m4.x : (q == 1) ? m4.y : (q == 2) ? m4.z : m4.w;
            unsigned idx = (unsigned)(i * 4 + q);
            bool p = valid && (m > Cm || (m == Cm && (~idx) >= Cl));
            unsigned bal = __ballot_sync(FULLM, p);
            int base = 0;
            if (lane == 0 && bal) base = (int)atomicAdd(&ctr[0], (unsigned)__popc(bal));
            base = __shfl_sync(FULLM, base, 0);
            if (p) {
                int pos = base + __popc(bal & ((1u << lane) - 1u));
                if (pos < 512)
                    defs[pos] = ((unsigned long long)m << 32) | (unsigned)(~idx);
            }
        }
    }
    __syncthreads();
    int cnt = min((int)ctr[0], 512);
    for (int i = cnt + tid; i < 512; i += NT) defs[i] = 0ull;
    __syncthreads();

    // ------- bitonic sort 512 u64 ascending, 2 elements per thread ---------
    {
        unsigned long long a0 = defs[tid];
        unsigned long long a1 = defs[tid + 256];
        for (int k = 2; k <= 512; k <<= 1) {
            for (int j = k >> 1; j > 0; j >>= 1) {
                if (j == 256) {
                    // partner pair lives in this thread (e=tid, e2=tid+256, k=512: asc)
                    if (a0 > a1) { unsigned long long t = a0; a0 = a1; a1 = t; }
                } else if (j >= 32) {
                    defs[tid] = a0; defs[tid + 256] = a1;
                    __syncthreads();
                    {
                        int e = tid;
                        unsigned long long pvv = defs[e ^ j];
                        bool ks = ((e & j) == 0) == ((e & k) == 0);
                        a0 = ((a0 < pvv) == ks) ? a0 : pvv;
                    }
                    {
                        int e = tid + 256;
                        unsigned long long pvv = defs[e ^ j];
                        bool ks = ((e & j) == 0) == ((e & k) == 0);
                        a1 = ((a1 < pvv) == ks) ? a1 : pvv;
                    }
                    __syncthreads();
                } else {
                    {
                        unsigned lo = (unsigned)a0, hi2 = (unsigned)(a0 >> 32);
                        unsigned plo = __shfl_xor_sync(FULLM, lo, j);
                        unsigned phi = __shfl_xor_sync(FULLM, hi2, j);
                        unsigned long long pvv = ((unsigned long long)phi << 32) | plo;
                        int e = tid;
                        bool ks = ((e & j) == 0) == ((e & k) == 0);
                        a0 = ((a0 < pvv) == ks) ? a0 : pvv;
                    }
                    {
                        unsigned lo = (unsigned)a1, hi2 = (unsigned)(a1 >> 32);
                        unsigned plo = __shfl_xor_sync(FULLM, lo, j);
                        unsigned phi = __shfl_xor_sync(FULLM, hi2, j);
                        unsigned long long pvv = ((unsigned long long)phi << 32) | plo;
                        int e = tid + 256;
                        bool ks = ((e & j) == 0) == ((e & k) == 0);
                        a1 = ((a1 < pvv) == ks) ? a1 : pvv;
                    }
                }
            }
        }
        defs[tid] = a0; defs[tid + 256] = a1;
        __syncthreads();
    }

    // ---------------- decode top-200 ---------------------------------------
    if (tid < TOPK) {
        unsigned long long key = defs[511 - tid];
        if (key) {
            unsigned m   = (unsigned)(key >> 32);
            unsigned idx = ~((unsigned)key);
            float sv = unmapf(m);
            float4 l  = __ldg((const float4*)loc + ((size_t)b * NP + idx));
            float4 pr = __ldg((const float4*)prior + idx);
            float cx = pr.x + l.x * 0.1f * pr.z;
            float cy = pr.y + l.y * 0.1f * pr.w;
            float w  = pr.z * expf(l.z * 0.2f);
            float h  = pr.w * expf(l.w * 0.2f);
            float x1 = cx - w * 0.5f;
            float y1 = cy - h * 0.5f;
            float x2 = x1 + w;
            float y2 = y1 + h;
            boxs[tid]  = make_float4(x1, y1, x2, y2);
            areas[tid] = (x2 - x1) * (y2 - y1);
            scores[tid] = sv;
        } else {
            boxs[tid]  = make_float4(0.f, 0.f, 0.f, 0.f);
            areas[tid] = 0.f;
            scores[tid] = -1.0f;
        }
    }
    for (int i = tid; i < TOPK * 8; i += NT) rows[i] = 0;
    __syncthreads();

    // ---------------- IoU bit-matrix: warp per (k-word, j-chunk) -----------
    {
        for (int tt = wid; tt < 28; tt += 8) {
            int w = 0;
            while ((w + 1) * (w + 2) / 2 <= tt) w++;
            int jc = tt - w * (w + 1) / 2;
            int k = w * 32 + lane;
            bool kv = k < TOPK;
            float4 bk = kv ? boxs[k] : make_float4(0.f, 0.f, 0.f, 0.f);
            float  ak = kv ? areas[k] : 0.f;
            int j0 = jc * 32, j1 = min(j0 + 32, TOPK);
            for (int j = j0; j < j1; j++) {
                float4 bj = boxs[j];
                float  aj = areas[j];
                bool hit = false;
                if (kv && k > j) {
                    float xx1 = fmaxf(bj.x, bk.x);
                    float yy1 = fmaxf(bj.y, bk.y);
                    float xx2 = fminf(bj.z, bk.z);
                    float yy2 = fminf(bj.w, bk.w);
                    float iw = fmaxf(xx2 - xx1, 0.0f);
                    float ih = fmaxf(yy2 - yy1, 0.0f);
                    float inter = iw * ih;
                    float uni = aj + ak - inter;
                    float iou = inter / uni;
                    hit = iou > 0.45f;
                }
                unsigned bal = __ballot_sync(FULLM, hit);
                if (lane == 0 && bal) rows[j * 8 + w] = bal;
            }
        }
    }
    __syncthreads();

    if (tid < 224) {
        int j = tid;
        bool val = (j < TOPK) && (scores[j] > 0.01f);
        unsigned r = 0;
        if (j < TOPK) {
            uint4 r1 = *(const uint4*)&rows[j * 8];
            uint4 r2 = *(const uint4*)&rows[j * 8 + 4];
            r = r1.x | r1.y | r1.z | r1.w | r2.x | r2.y | r2.z;
        }
        unsigned vb = __ballot_sync(FULLM, val);
        unsigned hb = __ballot_sync(FULLM, r != 0);
        if (lane == 0) { validw[wid] = vb; hasroww[wid] = hb; }
    }
    __syncthreads();

    // ---------------- serial greedy (bit ops) -------------------------------
    if (tid == 0) {
        unsigned sup[7] = {0, 0, 0, 0, 0, 0, 0};
        #pragma unroll
        for (int w = 0; w < 7; w++) {
            unsigned kwv = 0;
            unsigned rowm = hasroww[w];
            unsigned pend = validw[w] & ~sup[w];
            while (pend) {
                unsigned r = pend & rowm;
                if (!r) { kwv |= pend; break; }
                int bsh = __ffs(r) - 1;
                unsigned below = (1u << bsh) - 1u;
                kwv |= pend & below;
                kwv |= 1u << bsh;
                int j = w * 32 + bsh;
                uint4 r1 = *(const uint4*)&rows[j * 8];
                uint4 r2 = *(const uint4*)&rows[j * 8 + 4];
                sup[0] |= r1.x; sup[1] |= r1.y; sup[2] |= r1.z; sup[3] |= r1.w;
                sup[4] |= r2.x; sup[5] |= r2.y; sup[6] |= r2.z;
                unsigned above = ~((below << 1) | 1u);
                pend = validw[w] & ~sup[w] & above;
            }
            keepw[w] = kwv;
        }
    }
    __syncthreads();

    // ---------------- compact & write ---------------------------------------
    if (tid < TOPK) {
        int w = tid >> 5, bs = tid & 31;
        unsigned kwv = keepw[w];
        if ((kwv >> bs) & 1u) {
            int pos = 0;
            #pragma unroll
            for (int ww = 0; ww < 7; ww++) if (ww < w) pos += __popc(keepw[ww]);
            pos += __popc(kwv & ((1u << bs) - 1u));
            float4 bx = boxs[tid];
            float* row = outBase + pos * 5;
            row[0] = scores[tid];
            row[1] = bx.x;
            row[2] = bx.y;
            row[3] = bx.z;
            row[4] = bx.w;
        }
    }
}

// ---------------------------------------------------------------------------
extern "C" void kernel_launch(void* const* d_in, const int* in_sizes, int n_in,
                              void* d_out, int out_size) {
    const float* loc   = (const float*)d_in[0];
    const float* conf  = (const float*)d_in[1];
    const float* prior = (const float*)d_in[2];
    float* out = (float*)d_out;

    const int nt = (NP + TP - 1) / TP;          // 18
    transpose_kernel<<<NB * nt, 256>>>(conf);
    pivot_kernel<<<NB * NC, NT>>>();
    select_kernel<<<NB * NC, NT>>>(loc, prior, out);
}

// round 8
// speedup vs baseline: 1.2912x; 1.2912x over previous
#include <cuda_runtime.h>
#include <math.h>

#define NB   32
#define NP   8732
#define NC   21
#define TOPK 200
#define NT   512
#define NP4  (NP / 4)      // 2183
#define FULLM 0xFFFFFFFFu

// Transposed, thresholded, order-mapped confidences: key32[b][c][p]
__device__ unsigned g_confT[(size_t)NB * NC * NP];

// ---------------------------------------------------------------------------
// Kernel 1: transpose + threshold + monotonic map (vectorized, no atomics)
// ---------------------------------------------------------------------------
#define TP  512
#define S2S 516
__global__ void transpose_kernel(const float* __restrict__ conf) {
    __shared__ float s2[NC * S2S];
    const int nt  = (NP + TP - 1) / TP;     // 18
    const int b   = blockIdx.x / nt;
    const int t   = blockIdx.x % nt;
    const int p0  = t * TP;
    const int np  = min(TP, NP - p0);
    const float* src = conf + ((size_t)b * NP + p0) * NC;
    const int n  = np * NC;
    const int nv = n >> 2;
    const float4* src4 = (const float4*)src;

    for (int i = threadIdx.x; i < nv; i += blockDim.x) {
        float4 v = src4[i];
        int li = i * 4;
        #pragma unroll
        for (int q = 0; q < 4; q++) {
            int e = li + q;
            int p = e / NC;
            int c = e - p * NC;
            float f = (q == 0) ? v.x : (q == 1) ? v.y : (q == 2) ? v.z : v.w;
            s2[c * S2S + p] = f;
        }
    }
    __syncthreads();

    const int ng = np >> 2;
    for (int idx = threadIdx.x; idx < NC * ng; idx += blockDim.x) {
        int c = idx / ng;
        int g = idx - c * ng;
        int p = g * 4;
        float4 v = *(const float4*)&s2[c * S2S + p];
        uint4 o;
        {
            float sv = (v.x > 0.01f) ? v.x : -1.0f;
            unsigned u = __float_as_uint(sv);
            o.x = (u & 0x80000000u) ? ~u : (u | 0x80000000u);
        }
        {
            float sv = (v.y > 0.01f) ? v.y : -1.0f;
            unsigned u = __float_as_uint(sv);
            o.y = (u & 0x80000000u) ? ~u : (u | 0x80000000u);
        }
        {
            float sv = (v.z > 0.01f) ? v.z : -1.0f;
            unsigned u = __float_as_uint(sv);
            o.z = (u & 0x80000000u) ? ~u : (u | 0x80000000u);
        }
        {
            float sv = (v.w > 0.01f) ? v.w : -1.0f;
            unsigned u = __float_as_uint(sv);
            o.w = (u & 0x80000000u) ? ~u : (u | 0x80000000u);
        }
        *(uint4*)(g_confT + ((size_t)b * NC + c) * NP + p0 + p) = o;
    }
}

// ---------------------------------------------------------------------------
__device__ __forceinline__ float unmapf(unsigned m) {
    unsigned u = (m & 0x80000000u) ? (m ^ 0x80000000u) : ~m;
    return __uint_as_float(u);
}

// ---------------------------------------------------------------------------
// Kernel 2: sample-threshold + collect >= C, sort, decode, NMS, write
// ---------------------------------------------------------------------------
__global__ __launch_bounds__(NT, 4)
void select_kernel(const float* __restrict__ loc,
                   const float* __restrict__ prior,
                   float* __restrict__ out) {
    const int blk = blockIdx.x;
    const int b   = blk / NC;
    const int c   = blk % NC;
    const int tid = threadIdx.x;
    const int lane = tid & 31;
    const int wid  = tid >> 5;
    float* outBase = out + (size_t)blk * (TOPK * 5);

    {
        float4* ob4 = (float4*)outBase;
        for (int i = tid; i < (TOPK * 5) / 4; i += NT)
            ob4[i] = make_float4(0.f, 0.f, 0.f, 0.f);
    }
    if (c == 0) return;

    __shared__ unsigned ctr[8];
    __shared__ unsigned samp[1024];
    __shared__ unsigned long long defs[512];
    __shared__ float4   boxs[TOPK];
    __shared__ float    areas[TOPK];
    __shared__ float    scores[TOPK];
    __shared__ unsigned rows[TOPK * 8];
    __shared__ unsigned keepw[8];
    __shared__ unsigned validw[8];
    __shared__ unsigned hasroww[8];

    const unsigned* col  = g_confT + (size_t)blk * NP;
    const uint4*    col4 = (const uint4*)col;
    const int FULL_IT = NP4 / NT;           // 4
    const int TAIL    = NP4 - FULL_IT * NT; // 135

    // ---------------- sample 1024 keys, sort ascending (u32 bitonic) -------
    {
        unsigned a0 = col[tid * 8 + 4];
        unsigned a1 = col[(tid + 512) * 8 + 4];
        for (int k = 2; k <= 1024; k <<= 1) {
            for (int j = k >> 1; j > 0; j >>= 1) {
                if (j == 512) {
                    if (a0 > a1) { unsigned t = a0; a0 = a1; a1 = t; }
                } else if (j >= 32) {
                    samp[tid] = a0; samp[tid + 512] = a1;
                    __syncthreads();
                    {
                        int e = tid;
                        unsigned pvv = samp[e ^ j];
                        bool ks = ((e & j) == 0) == ((e & k) == 0);
                        a0 = ((a0 < pvv) == ks) ? a0 : pvv;
                    }
                    {
                        int e = tid + 512;
                        unsigned pvv = samp[e ^ j];
                        bool ks = ((e & j) == 0) == ((e & k) == 0);
                        a1 = ((a1 < pvv) == ks) ? a1 : pvv;
                    }
                    __syncthreads();
                } else {
                    {
                        unsigned pvv = __shfl_xor_sync(FULLM, a0, j);
                        int e = tid;
                        bool ks = ((e & j) == 0) == ((e & k) == 0);
                        a0 = ((a0 < pvv) == ks) ? a0 : pvv;
                    }
                    {
                        unsigned pvv = __shfl_xor_sync(FULLM, a1, j);
                        int e = tid + 512;
                        bool ks = ((e & j) == 0) == ((e & k) == 0);
                        a1 = ((a1 < pvv) == ks) ? a1 : pvv;
                    }
                }
            }
        }
        samp[tid] = a0; samp[tid + 512] = a1;
        __syncthreads();
    }

    // ---------------- collect keys >= C with sample-rank retry -------------
    unsigned Cm = 0, Cl = 0;
    int cnt = 0;
    {
        int rmin = 1, rmax = 1024, r = 40, attempts = 0;
        bool exact = false;
        while (true) {
            Cm = samp[1024 - r];
            Cl = 0;
            if (tid == 0) ctr[0] = 0;
            __syncthreads();
            for (int it = 0; it <= FULL_IT; it++) {
                int i = it * NT + tid;
                bool valid = (it < FULL_IT) || (tid < TAIL);
                uint4 m4 = valid ? col4[i] : make_uint4(0, 0, 0, 0);
                #pragma unroll
                for (int q = 0; q < 4; q++) {
                    unsigned m = (q == 0) ? m4.x : (q == 1) ? m4.y : (q == 2) ? m4.z : m4.w;
                    unsigned idx = (unsigned)(i * 4 + q);
                    bool p = valid && (m >= Cm);
                    unsigned bal = __ballot_sync(FULLM, p);
                    int base = 0;
                    if (lane == 0 && bal) base = (int)atomicAdd(&ctr[0], (unsigned)__popc(bal));
                    base = __shfl_sync(FULLM, base, 0);
                    if (p) {
                        int pos = base + __popc(bal & ((1u << lane) - 1u));
                        if (pos < 512)
                            defs[pos] = ((unsigned long long)m << 32) | (unsigned)(~idx);
                    }
                }
            }
            __syncthreads();
            cnt = (int)ctr[0];
            if (cnt >= TOPK && cnt <= 512) break;
            attempts++;
            if (cnt > 512) rmax = r - 1; else rmin = r + 1;
            if (attempts >= 6 || rmin > rmax) { exact = true; break; }
            r = (rmin + rmax) >> 1;
            __syncthreads();
        }

        if (exact) {
            // adversarial-input fallback: exact bitwise search on 64-bit keys
            unsigned long long Cp = 0;
            for (int bit = 63; bit >= 0; bit--) {
                unsigned long long trial = Cp | (1ull << bit);
                if (tid == 0) ctr[7] = 0;
                __syncthreads();
                unsigned wcnt = 0;
                for (int it = 0; it <= FULL_IT; it++) {
                    int i = it * NT + tid;
                    bool valid = (it < FULL_IT) || (tid < TAIL);
                    uint4 m4 = valid ? col4[i] : make_uint4(0, 0, 0, 0);
                    #pragma unroll
                    for (int q = 0; q < 4; q++) {
                        unsigned m = (q == 0) ? m4.x : (q == 1) ? m4.y : (q == 2) ? m4.z : m4.w;
                        unsigned idx = (unsigned)(i * 4 + q);
                        unsigned long long key =
                            ((unsigned long long)m << 32) | (unsigned)(~idx);
                        wcnt += __popc(__ballot_sync(FULLM, valid && key >= trial));
                    }
                }
                if (lane == 0) atomicAdd(&ctr[7], wcnt);
                __syncthreads();
                if (ctr[7] >= TOPK) Cp = trial;
                __syncthreads();
            }
            Cm = (unsigned)(Cp >> 32);
            Cl = (unsigned)Cp;
            if (tid == 0) ctr[0] = 0;
            __syncthreads();
            for (int it = 0; it <= FULL_IT; it++) {
                int i = it * NT + tid;
                bool valid = (it < FULL_IT) || (tid < TAIL);
                uint4 m4 = valid ? col4[i] : make_uint4(0, 0, 0, 0);
                #pragma unroll
                for (int q = 0; q < 4; q++) {
                    unsigned m = (q == 0) ? m4.x : (q == 1) ? m4.y : (q == 2) ? m4.z : m4.w;
                    unsigned idx = (unsigned)(i * 4 + q);
                    bool p = valid && (m > Cm || (m == Cm && (~idx) >= Cl));
                    unsigned bal = __ballot_sync(FULLM, p);
                    int base = 0;
                    if (lane == 0 && bal) base = (int)atomicAdd(&ctr[0], (unsigned)__popc(bal));
                    base = __shfl_sync(FULLM, base, 0);
                    if (p) {
                        int pos = base + __popc(bal & ((1u << lane) - 1u));
                        if (pos < 512)
                            defs[pos] = ((unsigned long long)m << 32) | (unsigned)(~idx);
                    }
                }
            }
            __syncthreads();
            cnt = min((int)ctr[0], 512);
        }
    }

    for (int i = cnt + tid; i < 512; i += NT) defs[i] = 0ull;
    __syncthreads();

    // ---------------- hybrid bitonic sort of 512 u64 (ascending) -----------
    {
        unsigned long long a = defs[tid];
        for (int k = 2; k <= 512; k <<= 1) {
            for (int j = k >> 1; j > 0; j >>= 1) {
                if (j >= 32) {
                    defs[tid] = a;
                    __syncthreads();
                    unsigned long long bb = defs[tid ^ j];
                    bool ks = (((tid & j) == 0) == ((tid & k) == 0));
                    a = ((a < bb) == ks) ? a : bb;
                    __syncthreads();
                } else {
                    unsigned lo = (unsigned)a, hi2 = (unsigned)(a >> 32);
                    unsigned plo = __shfl_xor_sync(FULLM, lo, j);
                    unsigned phi = __shfl_xor_sync(FULLM, hi2, j);
                    unsigned long long bb = ((unsigned long long)phi << 32) | plo;
                    bool ks = (((tid & j) == 0) == ((tid & k) == 0));
                    a = ((a < bb) == ks) ? a : bb;
                }
            }
        }
        defs[tid] = a;
        __syncthreads();
    }

    // ---------------- decode top-200 ---------------------------------------
    if (tid < TOPK) {
        unsigned long long key = defs[511 - tid];
        if (key) {
            unsigned m   = (unsigned)(key >> 32);
            unsigned idx = ~((unsigned)key);
            float sv = unmapf(m);
            float4 l  = __ldg((const float4*)loc + ((size_t)b * NP + idx));
            float4 pr = __ldg((const float4*)prior + idx);
            float cx = pr.x + l.x * 0.1f * pr.z;
            float cy = pr.y + l.y * 0.1f * pr.w;
            float w  = pr.z * expf(l.z * 0.2f);
            float h  = pr.w * expf(l.w * 0.2f);
            float x1 = cx - w * 0.5f;
            float y1 = cy - h * 0.5f;
            float x2 = x1 + w;
            float y2 = y1 + h;
            boxs[tid]  = make_float4(x1, y1, x2, y2);
            areas[tid] = (x2 - x1) * (y2 - y1);
            scores[tid] = sv;
        } else {
            boxs[tid]  = make_float4(0.f, 0.f, 0.f, 0.f);
            areas[tid] = 0.f;
            scores[tid] = -1.0f;
        }
    }
    for (int i = tid; i < TOPK * 8; i += NT) rows[i] = 0;
    __syncthreads();

    // ---------------- IoU bit-matrix: warp per (k-word, j-chunk) -----------
    {
        for (int tt = wid; tt < 28; tt += 16) {
            int w = 0;
            while ((w + 1) * (w + 2) / 2 <= tt) w++;
            int jc = tt - w * (w + 1) / 2;
            int k = w * 32 + lane;
            bool kv = k < TOPK;
            float4 bk = kv ? boxs[k] : make_float4(0.f, 0.f, 0.f, 0.f);
            float  ak = kv ? areas[k] : 0.f;
            int j0 = jc * 32, j1 = min(j0 + 32, TOPK);
            for (int j = j0; j < j1; j++) {
                float4 bj = boxs[j];
                float  aj = areas[j];
                bool hit = false;
                if (kv && k > j) {
                    float xx1 = fmaxf(bj.x, bk.x);
                    float yy1 = fmaxf(bj.y, bk.y);
                    float xx2 = fminf(bj.z, bk.z);
                    float yy2 = fminf(bj.w, bk.w);
                    float iw = fmaxf(xx2 - xx1, 0.0f);
                    float ih = fmaxf(yy2 - yy1, 0.0f);
                    float inter = iw * ih;
                    float uni = aj + ak - inter;
                    float iou = inter / uni;
                    hit = iou > 0.45f;
                }
                unsigned bal = __ballot_sync(FULLM, hit);
                if (lane == 0 && bal) rows[j * 8 + w] = bal;
            }
        }
    }
    __syncthreads();

    if (tid < 224) {
        int j = tid;
        bool val = (j < TOPK) && (scores[j] > 0.01f);
        unsigned r = 0;
        if (j < TOPK) {
            uint4 r1 = *(const uint4*)&rows[j * 8];
            uint4 r2 = *(const uint4*)&rows[j * 8 + 4];
            r = r1.x | r1.y | r1.z | r1.w | r2.x | r2.y | r2.z;
        }
        unsigned vb = __ballot_sync(FULLM, val);
        unsigned hb = __ballot_sync(FULLM, r != 0);
        if (lane == 0) { validw[wid] = vb; hasroww[wid] = hb; }
    }
    __syncthreads();

    // ---------------- serial greedy (bit ops) -------------------------------
    if (tid == 0) {
        unsigned sup[7] = {0, 0, 0, 0, 0, 0, 0};
        #pragma unroll
        for (int w = 0; w < 7; w++) {
            unsigned kwv = 0;
            unsigned rowm = hasroww[w];
            unsigned pend = validw[w] & ~sup[w];
            while (pend) {
                unsigned r = pend & rowm;
                if (!r) { kwv |= pend; break; }
                int bsh = __ffs(r) - 1;
                unsigned below = (1u << bsh) - 1u;
                kwv |= pend & below;
                kwv |= 1u << bsh;
                int j = w * 32 + bsh;
                uint4 r1 = *(const uint4*)&rows[j * 8];
                uint4 r2 = *(const uint4*)&rows[j * 8 + 4];
                sup[0] |= r1.x; sup[1] |= r1.y; sup[2] |= r1.z; sup[3] |= r1.w;
                sup[4] |= r2.x; sup[5] |= r2.y; sup[6] |= r2.z;
                unsigned above = ~((below << 1) | 1u);
                pend = validw[w] & ~sup[w] & above;
            }
            keepw[w] = kwv;
        }
    }
    __syncthreads();

    // ---------------- compact & write ---------------------------------------
    if (tid < TOPK) {
        int w = tid >> 5, bs = tid & 31;
        unsigned kwv = keepw[w];
        if ((kwv >> bs) & 1u) {
            int pos = 0;
            #pragma unroll
            for (int ww = 0; ww < 7; ww++) if (ww < w) pos += __popc(keepw[ww]);
            pos += __popc(kwv & ((1u << bs) - 1u));
            float4 bx = boxs[tid];
            float* row = outBase + pos * 5;
            row[0] = scores[tid];
            row[1] = bx.x;
            row[2] = bx.y;
            row[3] = bx.z;
            row[4] = bx.w;
        }
    }
}

// ---------------------------------------------------------------------------
extern "C" void kernel_launch(void* const* d_in, const int* in_sizes, int n_in,
                              void* d_out, int out_size) {
    const float* loc   = (const float*)d_in[0];
    const float* conf  = (const float*)d_in[1];
    const float* prior = (const float*)d_in[2];
    float* out = (float*)d_out;

    const int nt = (NP + TP - 1) / TP;          // 18
    transpose_kernel<<<NB * nt, 256>>>(conf);
    select_kernel<<<NB * NC, NT>>>(loc, prior, out);
}